// round 9
// baseline (speedup 1.0000x reference)
#include <cuda_runtime.h>
#include <cuda_bf16.h>
#include <math.h>
#include <stdint.h>

#define NNODES 50000
#define NEDGES 500000
#define CDIM   128
#define K3C    384

// tcgen05 is an arch-specific (sm_103a) feature; the harness also builds a
// base compute_103 pass where those instructions are illegal PTX. Guard them.
#if defined(__CUDA_ARCH__) && (defined(__CUDA_ARCH_FEAT_SM103_ALL) || defined(__CUDA_ARCH_FEAT_SM100_ALL) || defined(__CUDA_ARCH_FEAT_SM101_ALL))
#define HAS_TCGEN05 1
#else
#define HAS_TCGEN05 0
#endif

typedef unsigned long long ull;

// ---------------- scratch (device globals; no allocations allowed) ----------
__device__ float g_h  [NNODES * CDIM];
__device__ float g_m  [NNODES * CDIM];
__device__ float g_x  [NNODES * CDIM];
__device__ float g_agg[NNODES * CDIM];
__device__ float g_tot[NNODES * CDIM];
__device__ float g_gi [NNODES * K3C];
__device__ float g_gh [NNODES * K3C];
__device__ float g_z  [NNODES * CDIM];
// bf16 hi/lo activation buffers
__device__ __nv_bfloat16 g_mhi[NNODES * CDIM], g_mlo[NNODES * CDIM];
__device__ __nv_bfloat16 g_ahi[NNODES * CDIM], g_alo[NNODES * CDIM];
// bf16 hi/lo weights (converted once per launch)
__device__ __nv_bfloat16 g_wihh[6 * K3C * CDIM], g_wihl[6 * K3C * CDIM];
__device__ __nv_bfloat16 g_whhh[6 * K3C * CDIM], g_whhl[6 * K3C * CDIM];
__device__ __nv_bfloat16 g_cwh [18 * CDIM * CDIM], g_cwl[18 * CDIM * CDIM];
__device__ __nv_bfloat16 g_w1h [CDIM * CDIM],      g_w1l[CDIM * CDIM];
// edge bucketing
__device__ int g_cnt[3];
__device__ int g_off[4];
__device__ int g_cur[3];
__device__ int g_es [NEDGES];
__device__ int g_ed [NEDGES];

// ---------------- small helpers ----------------------------------------------
__device__ __forceinline__ uint32_t smem_u32(const void* p) {
    uint32_t a;
    asm("{ .reg .u64 t; cvta.to.shared.u64 t, %1; cvt.u32.u64 %0, t; }" : "=r"(a) : "l"(p));
    return a;
}
__device__ __forceinline__ bool elect1() {
    uint32_t p;
    asm volatile("{\n\t.reg .pred P;\n\telect.sync _|P, 0xFFFFFFFF;\n\tselp.b32 %0, 1, 0, P;\n\t}" : "=r"(p));
    return p != 0;
}
__device__ __forceinline__ void split_bf16(float v, __nv_bfloat16& h, __nv_bfloat16& l) {
    h = __float2bfloat16(v);
    l = __float2bfloat16(v - __bfloat162float(h));
}

// ---------------- tcgen05 GEMM: D[M,Ncols] = A[M,128] @ B[Ncols,128]^T -------
// fp32 via bf16 split: D = Ahi*Bhi + Ahi*Blo + Alo*Bhi (fp32 TMEM accumulate).
// idesc: dtype=F32, a/b=BF16, N=128 tile, M=128 (cross-checked vs test_mma.cu 0x8080490)
#define MMA_IDESC ((1u << 4) | (1u << 7) | (1u << 10) | ((128u / 8u) << 17) | ((128u / 16u) << 24))

// SW128 K-major smem descriptor base: layout=SW128(2), version=1, SBO=64, LBO=1
#define DESC_BASE ((2ULL << 61) | (1ULL << 46) | (64ULL << 32) | (1ULL << 16))
__device__ __forceinline__ ull mk_desc(uint32_t addr) {
    return DESC_BASE | (ull)((addr >> 4) & 0x3FFF);
}

// blocked-atom SW128 byte offset for a 128-row x 128-bf16col tile (2 atom cols)
__device__ __forceinline__ uint32_t tile_off(int r, int kc8) {
    uint32_t b = (uint32_t)(((r >> 3) + (kc8 >> 6) * 16) * 1024 + (r & 7) * 128 + (kc8 & 63) * 2);
    return b ^ ((b >> 3) & 0x70);
}

#if HAS_TCGEN05
__device__ __forceinline__ void mma_f16_ss(uint32_t d, ull ad, ull bd, uint32_t en) {
    asm volatile(
        "{\n\t"
        ".reg .pred p;\n\t"
        "setp.ne.u32 p, %5, 0;\n\t"
        "tcgen05.mma.cta_group::1.kind::f16 [%0], %1, %2, %3, {%4, %4, %4, %4}, p;\n\t"
        "}"
        :: "r"(d), "l"(ad), "l"(bd), "r"(MMA_IDESC), "r"(0u), "r"(en) : "memory");
}

#define LDTM_X32(r, addr) \
    asm volatile( \
        "tcgen05.ld.sync.aligned.32x32b.x32.b32 " \
        "{%0, %1, %2, %3, %4, %5, %6, %7, " \
        " %8, %9, %10, %11, %12, %13, %14, %15, " \
        " %16, %17, %18, %19, %20, %21, %22, %23, " \
        " %24, %25, %26, %27, %28, %29, %30, %31}, [%32];" \
        : "=r"((r)[0]),  "=r"((r)[1]),  "=r"((r)[2]),  "=r"((r)[3]), \
          "=r"((r)[4]),  "=r"((r)[5]),  "=r"((r)[6]),  "=r"((r)[7]), \
          "=r"((r)[8]),  "=r"((r)[9]),  "=r"((r)[10]), "=r"((r)[11]), \
          "=r"((r)[12]), "=r"((r)[13]), "=r"((r)[14]), "=r"((r)[15]), \
          "=r"((r)[16]), "=r"((r)[17]), "=r"((r)[18]), "=r"((r)[19]), \
          "=r"((r)[20]), "=r"((r)[21]), "=r"((r)[22]), "=r"((r)[23]), \
          "=r"((r)[24]), "=r"((r)[25]), "=r"((r)[26]), "=r"((r)[27]), \
          "=r"((r)[28]), "=r"((r)[29]), "=r"((r)[30]), "=r"((r)[31]) \
        : "r"(addr))
#endif

__device__ __forceinline__ void mbar_wait0(uint32_t mbar) {
    uint32_t done;
    do {
        asm volatile(
            "{\n\t.reg .pred p;\n\t"
            "mbarrier.try_wait.parity.acquire.cta.shared::cta.b64 p, [%1], %2, 0x989680;\n\t"
            "selp.b32 %0, 1, 0, p;\n\t}"
            : "=r"(done) : "r"(mbar), "r"(0u) : "memory");
    } while (!done);
}

// smem layout (dynamic): tmem ptr @0, mbar @8, bias @512, 4x 32KB tiles @1024
#define SO_TM   0
#define SO_MBAR 8
#define SO_BIAS 512
#define SO_AHI  1024
#define SO_BHI  (1024 + 32768)
#define SO_ALO  (1024 + 65536)
#define SO_BLO  (1024 + 98304)
#define SMEM_BYTES 132096

__device__ __forceinline__ void load_tile(char* dstbase, const __nv_bfloat16* __restrict__ G,
                                          int row0, int rowLimit, int tid) {
    for (int q = tid; q < 2048; q += 256) {
        int r   = q >> 4;
        int kc8 = (q & 15) << 3;
        uint4 v = make_uint4(0u, 0u, 0u, 0u);
        int gr = row0 + r;
        if (gr < rowLimit)
            v = *reinterpret_cast<const uint4*>(G + (long)gr * 128 + kc8);
        *reinterpret_cast<uint4*>(dstbase + tile_off(r, kc8)) = v;
    }
}

template <int RELU>
__global__ __launch_bounds__(256)
void mma_gemm(const __nv_bfloat16* __restrict__ Ahi, const __nv_bfloat16* __restrict__ Alo,
              const __nv_bfloat16* __restrict__ Bhi, const __nv_bfloat16* __restrict__ Blo,
              const float* __restrict__ bias, float* __restrict__ C,
              int M, int Ncols) {
#if HAS_TCGEN05
    extern __shared__ __align__(16) char smem[];
    const int tid  = threadIdx.x;
    const int wid  = tid >> 5;
    const int lid  = tid & 31;
    const int brow = blockIdx.x * 128;
    const int bcol = blockIdx.y * 128;
    uint32_t sb = smem_u32(smem);

    if (tid == 0)
        asm volatile("mbarrier.init.shared.b64 [%0], 1;" :: "r"(sb + SO_MBAR) : "memory");
    if (wid == 0) {
        asm volatile("tcgen05.alloc.cta_group::1.sync.aligned.shared::cta.b32 [%0], %1;"
                     :: "r"(sb + SO_TM), "r"(128u) : "memory");
        asm volatile("tcgen05.relinquish_alloc_permit.cta_group::1.sync.aligned;");
    }
    if (tid < 128)
        reinterpret_cast<float*>(smem + SO_BIAS)[tid] = bias ? bias[bcol + tid] : 0.0f;

    // phase 1: hi tiles
    load_tile(smem + SO_AHI, Ahi, brow, M, tid);
    load_tile(smem + SO_BHI, Bhi, bcol, 1 << 30, tid);
    __syncthreads();

    uint32_t tb;
    asm volatile("ld.shared.b32 %0, [%1];" : "=r"(tb) : "r"(sb + SO_TM));

    ull adh = mk_desc(sb + SO_AHI);
    ull bdh = mk_desc(sb + SO_BHI);
    if (wid == 0 && elect1()) {
        asm volatile("fence.proxy.async.shared::cta;" ::: "memory");
#pragma unroll
        for (int kk = 0; kk < 8; kk++) {
            uint32_t off = (uint32_t)((kk >> 2) * 1024 + (kk & 3) * 2);
            mma_f16_ss(tb, adh + off, bdh + off, kk > 0 ? 1u : 0u);
        }
    }

    // phase 2: lo tiles (overlaps with in-flight hi MMAs)
    load_tile(smem + SO_ALO, Alo, brow, M, tid);
    load_tile(smem + SO_BLO, Blo, bcol, 1 << 30, tid);
    __syncthreads();

    if (wid == 0 && elect1()) {
        asm volatile("fence.proxy.async.shared::cta;" ::: "memory");
        ull adl = mk_desc(sb + SO_ALO);
        ull bdl = mk_desc(sb + SO_BLO);
#pragma unroll
        for (int kk = 0; kk < 8; kk++) {
            uint32_t off = (uint32_t)((kk >> 2) * 1024 + (kk & 3) * 2);
            mma_f16_ss(tb, adh + off, bdl + off, 1u);
        }
#pragma unroll
        for (int kk = 0; kk < 8; kk++) {
            uint32_t off = (uint32_t)((kk >> 2) * 1024 + (kk & 3) * 2);
            mma_f16_ss(tb, adl + off, bdh + off, 1u);
        }
        asm volatile("tcgen05.commit.cta_group::1.mbarrier::arrive::one.shared::cluster.b64 [%0];"
                     :: "r"(sb + SO_MBAR) : "memory");
    }

    mbar_wait0(sb + SO_MBAR);
    asm volatile("tcgen05.fence::after_thread_sync;" ::: "memory");

    // epilogue: warps 0-3 cols 0-63, warps 4-7 cols 64-127 for the same rows.
    const float* sbias = reinterpret_cast<const float*>(smem + SO_BIAS);
    int half = wid >> 2;
    int grow = brow + (wid & 3) * 32 + lid;
    uint32_t dr[32];
#pragma unroll
    for (int cb = 0; cb < 2; cb++) {
        int cbase = half * 64 + cb * 32;
        LDTM_X32(dr, tb + cbase);
        asm volatile("tcgen05.wait::ld.sync.aligned;" ::: "memory");
        if (grow < M) {
#pragma unroll
            for (int c = 0; c < 32; c += 4) {
                float4 v;
                v.x = __uint_as_float(dr[c + 0]) + sbias[cbase + c + 0];
                v.y = __uint_as_float(dr[c + 1]) + sbias[cbase + c + 1];
                v.z = __uint_as_float(dr[c + 2]) + sbias[cbase + c + 2];
                v.w = __uint_as_float(dr[c + 3]) + sbias[cbase + c + 3];
                if (RELU) {
                    v.x = fmaxf(v.x, 0.f); v.y = fmaxf(v.y, 0.f);
                    v.z = fmaxf(v.z, 0.f); v.w = fmaxf(v.w, 0.f);
                }
                *reinterpret_cast<float4*>(C + (long)grow * Ncols + bcol + cbase + c) = v;
            }
        }
    }
    asm volatile("tcgen05.fence::before_thread_sync;" ::: "memory");
    __syncthreads();
    if (wid == 0)
        asm volatile("tcgen05.dealloc.cta_group::1.sync.aligned.b32 %0, %1;"
                     :: "r"(tb), "r"(128u));
#else
    // ---- correct scalar fallback (base-arch compile pass; not expected to run
    //      on the GB300 since the loader prefers the sm_103a cubin) ----
    const int tid  = threadIdx.x;
    const int brow = blockIdx.x * 128;
    const int bcol = blockIdx.y * 128;
    int r   = tid >> 1;
    int gr  = brow + r;
    if (gr >= M) return;
    int c0  = (tid & 1) * 64;
    for (int cc = 0; cc < 64; cc++) {
        int col = c0 + cc;
        float acc = bias ? bias[bcol + col] : 0.0f;
        const __nv_bfloat16* ah = Ahi + (long)gr * 128;
        const __nv_bfloat16* al = Alo + (long)gr * 128;
        const __nv_bfloat16* bh = Bhi + (long)(bcol + col) * 128;
        const __nv_bfloat16* bl = Blo + (long)(bcol + col) * 128;
        for (int k = 0; k < 128; k++) {
            float a = __bfloat162float(ah[k]) + __bfloat162float(al[k]);
            float b = __bfloat162float(bh[k]) + __bfloat162float(bl[k]);
            acc += a * b;
        }
        if (RELU) acc = fmaxf(acc, 0.0f);
        C[(long)gr * Ncols + bcol + col] = acc;
    }
#endif
}

// ---------------- weight conversion (once per launch) ------------------------
__global__ void cvt_pair(const float* __restrict__ src, __nv_bfloat16* __restrict__ hi,
                         __nv_bfloat16* __restrict__ lo, int n4) {
    int idx = blockIdx.x * blockDim.x + threadIdx.x;
    if (idx >= n4) return;
    float4 v = reinterpret_cast<const float4*>(src)[idx];
    ushort4 h, l;
    __nv_bfloat16 bh, bl;
    split_bf16(v.x, bh, bl); h.x = __bfloat16_as_ushort(bh); l.x = __bfloat16_as_ushort(bl);
    split_bf16(v.y, bh, bl); h.y = __bfloat16_as_ushort(bh); l.y = __bfloat16_as_ushort(bl);
    split_bf16(v.z, bh, bl); h.z = __bfloat16_as_ushort(bh); l.z = __bfloat16_as_ushort(bl);
    split_bf16(v.w, bh, bl); h.w = __bfloat16_as_ushort(bh); l.w = __bfloat16_as_ushort(bl);
    reinterpret_cast<ushort4*>(hi)[idx] = h;
    reinterpret_cast<ushort4*>(lo)[idx] = l;
}

// transpose each 128x128 matrix: out[m][co][k] = in[m][k][co]
__global__ void cvt_trans(const float* __restrict__ src, __nv_bfloat16* __restrict__ hi,
                          __nv_bfloat16* __restrict__ lo, int nmat) {
    int idx = blockIdx.x * blockDim.x + threadIdx.x;
    if (idx >= nmat * 16384) return;
    int m  = idx >> 14;
    int co = (idx >> 7) & 127;
    int k  = idx & 127;
    float v = src[m * 16384 + k * 128 + co];
    __nv_bfloat16 bh, bl;
    split_bf16(v, bh, bl);
    hi[idx] = bh;
    lo[idx] = bl;
}

// copy/convert activation: dstf (optional) = src; hi/lo = bf16 split of src
__global__ void copy_cvt(const float* __restrict__ src, float* __restrict__ dstf,
                         __nv_bfloat16* __restrict__ hi, __nv_bfloat16* __restrict__ lo) {
    int idx = blockIdx.x * blockDim.x + threadIdx.x;
    if (idx >= NNODES * 32) return;
    float4 v = reinterpret_cast<const float4*>(src)[idx];
    if (dstf) reinterpret_cast<float4*>(dstf)[idx] = v;
    ushort4 h, l;
    __nv_bfloat16 bh, bl;
    split_bf16(v.x, bh, bl); h.x = __bfloat16_as_ushort(bh); l.x = __bfloat16_as_ushort(bl);
    split_bf16(v.y, bh, bl); h.y = __bfloat16_as_ushort(bh); l.y = __bfloat16_as_ushort(bl);
    split_bf16(v.z, bh, bl); h.z = __bfloat16_as_ushort(bh); l.z = __bfloat16_as_ushort(bl);
    split_bf16(v.w, bh, bl); h.w = __bfloat16_as_ushort(bh); l.w = __bfloat16_as_ushort(bl);
    reinterpret_cast<ushort4*>(hi)[idx] = h;
    reinterpret_cast<ushort4*>(lo)[idx] = l;
}

// ---------------- feature build ---------------------------------------------
__global__ void build_features(const int* __restrict__ xt,
                               const int* __restrict__ xtok,
                               const float* __restrict__ xs) {
    int idx = blockIdx.x * blockDim.x + threadIdx.x;
    if (idx >= NNODES * CDIM) return;
    int n = idx >> 7;
    int c = idx & 127;
    float v;
    if (c < 32) {
        v = (c == xt[n]) ? 1.0f : 0.0f;
    } else if (c < 126) {
        int tok = xtok[n];
        tok = min(max(tok, 0), 93);
        v = ((c - 32) == tok) ? 1.0f : 0.0f;
    } else {
        v = xs[n * 2 + (c - 126)];
    }
    g_h[idx] = v;
}

// ---------------- edge bucketing (block-aggregated atomics) ------------------
__global__ void count_et_blk(const int* __restrict__ et) {
    __shared__ int loc[3];
    if (threadIdx.x < 3) loc[threadIdx.x] = 0;
    __syncthreads();
    int e = blockIdx.x * blockDim.x + threadIdx.x;
    if (e < NEDGES) atomicAdd(&loc[et[e]], 1);
    __syncthreads();
    if (threadIdx.x < 3 && loc[threadIdx.x] > 0) atomicAdd(&g_cnt[threadIdx.x], loc[threadIdx.x]);
}
__global__ void prefix_et() {
    g_off[0] = 0;
    g_off[1] = g_cnt[0];
    g_off[2] = g_cnt[0] + g_cnt[1];
    g_off[3] = g_cnt[0] + g_cnt[1] + g_cnt[2];
    g_cur[0] = 0;
    g_cur[1] = g_cnt[0];
    g_cur[2] = g_cnt[0] + g_cnt[1];
}
__global__ void bucket_et_blk(const int* __restrict__ ei, const int* __restrict__ et) {
    __shared__ int loc[3], base[3];
    if (threadIdx.x < 3) loc[threadIdx.x] = 0;
    __syncthreads();
    int e = blockIdx.x * blockDim.x + threadIdx.x;
    int t = 0, rank = 0;
    bool valid = (e < NEDGES);
    if (valid) {
        t = et[e];
        rank = atomicAdd(&loc[t], 1);
    }
    __syncthreads();
    if (threadIdx.x < 3) base[threadIdx.x] = (loc[threadIdx.x] > 0) ? atomicAdd(&g_cur[threadIdx.x], loc[threadIdx.x]) : 0;
    __syncthreads();
    if (valid) {
        int p = base[t] + rank;
        g_es[p] = ei[e];
        g_ed[p] = ei[NEDGES + e];
    }
}

// ---------------- scatter-add over bucketed edges ----------------------------
__global__ void scatter_add(int t) {
    long idx = (long)blockIdx.x * blockDim.x + threadIdx.x;
    int e = (int)(idx >> 5);
    int lo = g_off[t], hi = g_off[t + 1];
    if (e < lo || e >= hi) return;
    int lane = (int)(idx & 31);
    int s = g_es[e];
    int d = g_ed[e];
    float4 v = *reinterpret_cast<const float4*>(g_x + (long)s * 128 + lane * 4);
    float* o = g_agg + (long)d * 128 + lane * 4;
    atomicAdd(o + 0, v.x);
    atomicAdd(o + 1, v.y);
    atomicAdd(o + 2, v.z);
    atomicAdd(o + 3, v.w);
}

// ---------------- GRU gate + bf16 split of new m + optional total accum ------
__global__ void gru_gate(int addTot) {
    int idx = blockIdx.x * blockDim.x + threadIdx.x;
    if (idx >= NNODES * 32) return;
    int n  = idx >> 5;
    int c4 = (idx & 31) * 4;
    const float* gi = g_gi + (long)n * K3C;
    const float* gh = g_gh + (long)n * K3C;
    float4 gir = *reinterpret_cast<const float4*>(gi + c4);
    float4 ghr = *reinterpret_cast<const float4*>(gh + c4);
    float4 giz = *reinterpret_cast<const float4*>(gi + 128 + c4);
    float4 ghz = *reinterpret_cast<const float4*>(gh + 128 + c4);
    float4 gin = *reinterpret_cast<const float4*>(gi + 256 + c4);
    float4 ghn = *reinterpret_cast<const float4*>(gh + 256 + c4);
    float4 hv  = *reinterpret_cast<const float4*>(g_m + (long)n * 128 + c4);
    float4 res;
#pragma unroll
    for (int j = 0; j < 4; j++) {
        float r  = 1.0f / (1.0f + expf(-((&gir.x)[j] + (&ghr.x)[j])));
        float z  = 1.0f / (1.0f + expf(-((&giz.x)[j] + (&ghz.x)[j])));
        float ng = tanhf((&gin.x)[j] + r * (&ghn.x)[j]);
        (&res.x)[j] = (1.0f - z) * ng + z * (&hv.x)[j];
    }
    *reinterpret_cast<float4*>(g_m + (long)n * 128 + c4) = res;
    ushort4 h, l;
    __nv_bfloat16 bh, bl;
    split_bf16(res.x, bh, bl); h.x = __bfloat16_as_ushort(bh); l.x = __bfloat16_as_ushort(bl);
    split_bf16(res.y, bh, bl); h.y = __bfloat16_as_ushort(bh); l.y = __bfloat16_as_ushort(bl);
    split_bf16(res.z, bh, bl); h.z = __bfloat16_as_ushort(bh); l.z = __bfloat16_as_ushort(bl);
    split_bf16(res.w, bh, bl); h.w = __bfloat16_as_ushort(bh); l.w = __bfloat16_as_ushort(bl);
    reinterpret_cast<ushort4*>(g_mhi)[idx] = h;
    reinterpret_cast<ushort4*>(g_mlo)[idx] = l;
    if (addTot) {
        float4 tv = *reinterpret_cast<const float4*>(g_tot + (long)n * 128 + c4);
        tv.x += res.x; tv.y += res.y; tv.z += res.z; tv.w += res.w;
        *reinterpret_cast<float4*>(g_tot + (long)n * 128 + c4) = tv;
    }
}

// ---------------- LayerNorm(residual) + ReLU ---------------------------------
__global__ void ln_relu(const float* __restrict__ gam, const float* __restrict__ bet) {
    int n = blockIdx.x;
    int c = threadIdx.x;
    float v  = g_h[(long)n * 128 + c] + g_tot[(long)n * 128 + c];
    float s  = v;
    float s2 = v * v;
#pragma unroll
    for (int o = 16; o; o >>= 1) {
        s  += __shfl_xor_sync(0xffffffffu, s,  o);
        s2 += __shfl_xor_sync(0xffffffffu, s2, o);
    }
    __shared__ float sh[4], sh2[4];
    int w = c >> 5;
    if ((c & 31) == 0) { sh[w] = s; sh2[w] = s2; }
    __syncthreads();
    s  = sh[0] + sh[1] + sh[2] + sh[3];
    s2 = sh2[0] + sh2[1] + sh2[2] + sh2[3];
    float mu  = s * (1.0f / 128.0f);
    float var = s2 * (1.0f / 128.0f) - mu * mu;
    float o = (v - mu) * rsqrtf(var + 1e-5f) * gam[c] + bet[c];
    g_h[(long)n * 128 + c] = fmaxf(o, 0.0f);
}

// ---------------- final tiny head: out = z @ w2^T + b2 -----------------------
__global__ void head2(const float* __restrict__ w2, const float* __restrict__ b2,
                      float* __restrict__ out) {
    int gw = (blockIdx.x * blockDim.x + threadIdx.x) >> 5;
    if (gw >= NNODES) return;
    int lane = threadIdx.x & 31;
    float4 zv = *reinterpret_cast<const float4*>(g_z + (long)gw * 128 + lane * 4);
    float4 w0 = *reinterpret_cast<const float4*>(w2 + lane * 4);
    float4 w1 = *reinterpret_cast<const float4*>(w2 + 128 + lane * 4);
    float p0 = zv.x * w0.x + zv.y * w0.y + zv.z * w0.z + zv.w * w0.w;
    float p1 = zv.x * w1.x + zv.y * w1.y + zv.z * w1.z + zv.w * w1.w;
#pragma unroll
    for (int o = 16; o; o >>= 1) {
        p0 += __shfl_xor_sync(0xffffffffu, p0, o);
        p1 += __shfl_xor_sync(0xffffffffu, p1, o);
    }
    if (lane == 0) {
        out[gw * 2 + 0] = p0 + b2[0];
        out[gw * 2 + 1] = p1 + b2[1];
    }
}

// ---------------- host orchestration -----------------------------------------
extern "C" void kernel_launch(void* const* d_in, const int* in_sizes, int n_in,
                              void* d_out, int out_size) {
    const int*   x_type  = (const int*)d_in[0];
    const int*   x_tok   = (const int*)d_in[1];
    const float* x_small = (const float*)d_in[2];
    const int*   ei      = (const int*)d_in[3];
    const int*   et      = (const int*)d_in[4];
    const float* conv_w  = (const float*)d_in[5];
    const float* wih     = (const float*)d_in[6];
    const float* whh     = (const float*)d_in[7];
    const float* bih     = (const float*)d_in[8];
    const float* bhh     = (const float*)d_in[9];
    const float* ln_g    = (const float*)d_in[10];
    const float* ln_b    = (const float*)d_in[11];
    const float* hw1     = (const float*)d_in[12];
    const float* hb1     = (const float*)d_in[13];
    const float* hw2     = (const float*)d_in[14];
    const float* hb2     = (const float*)d_in[15];
    float* out = (float*)d_out;

    cudaFuncSetAttribute(mma_gemm<0>, cudaFuncAttributeMaxDynamicSharedMemorySize, SMEM_BYTES);
    cudaFuncSetAttribute(mma_gemm<1>, cudaFuncAttributeMaxDynamicSharedMemorySize, SMEM_BYTES);

    float *h_, *m_, *x_, *agg_, *tot_, *gi_, *gh_, *z_;
    __nv_bfloat16 *mhi_, *mlo_, *ahi_, *alo_;
    __nv_bfloat16 *wihh_, *wihl_, *whhh_, *whhl_, *cwh_, *cwl_, *w1h_, *w1l_;
    int* cnt_;
    cudaGetSymbolAddress((void**)&h_,   g_h);
    cudaGetSymbolAddress((void**)&m_,   g_m);
    cudaGetSymbolAddress((void**)&x_,   g_x);
    cudaGetSymbolAddress((void**)&agg_, g_agg);
    cudaGetSymbolAddress((void**)&tot_, g_tot);
    cudaGetSymbolAddress((void**)&gi_,  g_gi);
    cudaGetSymbolAddress((void**)&gh_,  g_gh);
    cudaGetSymbolAddress((void**)&z_,   g_z);
    cudaGetSymbolAddress((void**)&mhi_, g_mhi);
    cudaGetSymbolAddress((void**)&mlo_, g_mlo);
    cudaGetSymbolAddress((void**)&ahi_, g_ahi);
    cudaGetSymbolAddress((void**)&alo_, g_alo);
    cudaGetSymbolAddress((void**)&wihh_, g_wihh);
    cudaGetSymbolAddress((void**)&wihl_, g_wihl);
    cudaGetSymbolAddress((void**)&whhh_, g_whhh);
    cudaGetSymbolAddress((void**)&whhl_, g_whhl);
    cudaGetSymbolAddress((void**)&cwh_, g_cwh);
    cudaGetSymbolAddress((void**)&cwl_, g_cwl);
    cudaGetSymbolAddress((void**)&w1h_, g_w1h);
    cudaGetSymbolAddress((void**)&w1l_, g_w1l);
    cudaGetSymbolAddress((void**)&cnt_, g_cnt);

    const size_t NC_BYTES = (size_t)NNODES * CDIM * sizeof(float);
    const int NC_GRID = (NNODES * CDIM + 255) / 256;
    const int NQ_GRID = (NNODES * 32 + 255) / 256;
    const int E_GRID  = (NEDGES + 255) / 256;
    const int SC_GRID = (int)(((long)NEDGES * 32 + 255) / 256);

    build_features<<<NC_GRID, 256>>>(x_type, x_tok, x_small);

    cudaMemsetAsync(cnt_, 0, 3 * sizeof(int));
    count_et_blk<<<E_GRID, 256>>>(et);
    prefix_et<<<1, 1>>>();
    bucket_et_blk<<<E_GRID, 256>>>(ei, et);

    // weight conversion (once per launch)
    cvt_pair<<<(6 * K3C * CDIM / 4 + 255) / 256, 256>>>(wih, wihh_, wihl_, 6 * K3C * CDIM / 4);
    cvt_pair<<<(6 * K3C * CDIM / 4 + 255) / 256, 256>>>(whh, whhh_, whhl_, 6 * K3C * CDIM / 4);
    cvt_pair<<<(CDIM * CDIM / 4 + 255) / 256, 256>>>(hw1, w1h_, w1l_, CDIM * CDIM / 4);
    cvt_trans<<<(18 * CDIM * CDIM + 255) / 256, 256>>>(conv_w, cwh_, cwl_, 18);

    dim3 g1((NNODES + 127) / 128, 1);
    dim3 g3((NNODES + 127) / 128, 3);

    for (int b = 0; b < 2; b++) {
        cudaMemsetAsync(tot_, 0, NC_BYTES);
        for (int t = 0; t < 3; t++) {
            copy_cvt<<<NQ_GRID, 256>>>(h_, m_, mhi_, mlo_);
            for (int s = 0; s < 3; s++) {
                int mi = ((b * 3) + t) * 3 + s;
                mma_gemm<0><<<g1, 256, SMEM_BYTES>>>(mhi_, mlo_,
                    cwh_ + (size_t)mi * CDIM * CDIM, cwl_ + (size_t)mi * CDIM * CDIM,
                    nullptr, x_, NNODES, CDIM);
                cudaMemsetAsync(agg_, 0, NC_BYTES);
                scatter_add<<<SC_GRID, 256>>>(t);
                copy_cvt<<<NQ_GRID, 256>>>(agg_, nullptr, ahi_, alo_);
                int wi = b * 3 + t;
                mma_gemm<0><<<g3, 256, SMEM_BYTES>>>(ahi_, alo_,
                    wihh_ + (size_t)wi * K3C * CDIM, wihl_ + (size_t)wi * K3C * CDIM,
                    bih + (size_t)wi * K3C, gi_, NNODES, K3C);
                mma_gemm<0><<<g3, 256, SMEM_BYTES>>>(mhi_, mlo_,
                    whhh_ + (size_t)wi * K3C * CDIM, whhl_ + (size_t)wi * K3C * CDIM,
                    bhh + (size_t)wi * K3C, gh_, NNODES, K3C);
                gru_gate<<<NQ_GRID, 256>>>(s == 2 ? 1 : 0);
            }
        }
        ln_relu<<<NNODES, 128>>>(ln_g + b * 128, ln_b + b * 128);
    }

    copy_cvt<<<NQ_GRID, 256>>>(h_, nullptr, mhi_, mlo_);
    mma_gemm<1><<<g1, 256, SMEM_BYTES>>>(mhi_, mlo_, w1h_, w1l_, hb1, z_, NNODES, CDIM);
    head2<<<(NNODES * 32 + 255) / 256, 256>>>(hw2, hb2, out);
}

// round 13
// speedup vs baseline: 1.5465x; 1.5465x over previous
#include <cuda_runtime.h>
#include <cuda_bf16.h>
#include <math.h>
#include <stdint.h>

#define NNODES 50000
#define NEDGES 500000
#define CDIM   128
#define K3C    384

// tcgen05 is an arch-specific (sm_103a) feature; the harness also builds a
// base compute_103 pass where those instructions are illegal PTX. Guard them.
#if defined(__CUDA_ARCH__) && (defined(__CUDA_ARCH_FEAT_SM103_ALL) || defined(__CUDA_ARCH_FEAT_SM100_ALL) || defined(__CUDA_ARCH_FEAT_SM101_ALL))
#define HAS_TCGEN05 1
#else
#define HAS_TCGEN05 0
#endif

typedef unsigned long long ull;

// ---------------- scratch (device globals; no allocations allowed) ----------
__device__ float g_h  [NNODES * CDIM];
__device__ float g_m  [NNODES * CDIM];
__device__ float g_x  [NNODES * CDIM];
__device__ float g_agg[NNODES * CDIM];
__device__ float g_tot[NNODES * CDIM];
__device__ float g_gi [NNODES * K3C];
__device__ float g_gh [NNODES * K3C];
__device__ float g_z  [NNODES * CDIM];
// bf16 hi/lo activation buffers
__device__ __nv_bfloat16 g_mhi[NNODES * CDIM], g_mlo[NNODES * CDIM];
__device__ __nv_bfloat16 g_ahi[NNODES * CDIM], g_alo[NNODES * CDIM];
// bf16 hi/lo weights (converted once per launch)
__device__ __nv_bfloat16 g_wihh[6 * K3C * CDIM], g_wihl[6 * K3C * CDIM];
__device__ __nv_bfloat16 g_whhh[6 * K3C * CDIM], g_whhl[6 * K3C * CDIM];
__device__ __nv_bfloat16 g_cwh [18 * CDIM * CDIM], g_cwl[18 * CDIM * CDIM];
__device__ __nv_bfloat16 g_w1h [CDIM * CDIM],      g_w1l[CDIM * CDIM];
// edge bucketing
__device__ int g_cnt[3];
__device__ int g_off[4];
__device__ int g_cur[3];
__device__ int g_es [NEDGES];
__device__ int g_ed [NEDGES];

// ---------------- small helpers ----------------------------------------------
__device__ __forceinline__ uint32_t smem_u32(const void* p) {
    uint32_t a;
    asm("{ .reg .u64 t; cvta.to.shared.u64 t, %1; cvt.u32.u64 %0, t; }" : "=r"(a) : "l"(p));
    return a;
}
__device__ __forceinline__ bool elect1() {
    uint32_t p;
    asm volatile("{\n\t.reg .pred P;\n\telect.sync _|P, 0xFFFFFFFF;\n\tselp.b32 %0, 1, 0, P;\n\t}" : "=r"(p));
    return p != 0;
}
__device__ __forceinline__ void split_bf16(float v, __nv_bfloat16& h, __nv_bfloat16& l) {
    h = __float2bfloat16(v);
    l = __float2bfloat16(v - __bfloat162float(h));
}

// ---------------- tcgen05 GEMM: D[M,Ncols] = A[M,128] @ B[Ncols,128]^T -------
// fp32 via bf16 split: D = Ahi*Bhi + Ahi*Blo + Alo*Bhi (fp32 TMEM accumulate).
// Tile: 128 M x 64 N, K=128. idesc: dtype=F32, a/b=BF16, N=64, M=128
// (encoding cross-checked vs test_mma.cu 0x8080490 for M=128,N=32)
#define MMA_IDESC ((1u << 4) | (1u << 7) | (1u << 10) | ((64u / 8u) << 17) | ((128u / 16u) << 24))

// SW128 K-major smem descriptor base: layout=SW128(2), version=1, SBO=64, LBO=1
#define DESC_BASE ((2ULL << 61) | (1ULL << 46) | (64ULL << 32) | (1ULL << 16))
__device__ __forceinline__ ull mk_desc(uint32_t addr) {
    return DESC_BASE | (ull)((addr >> 4) & 0x3FFF);
}

// blocked-atom SW128 byte offsets (atom = 8 rows x 64 bf16 = 1KB)
// A tile: 128 rows -> 16 atom-rows per atom-col; B tile: 64 rows -> 8 atom-rows.
__device__ __forceinline__ uint32_t tile_off_a(int r, int kc8) {
    uint32_t b = (uint32_t)(((r >> 3) + (kc8 >> 6) * 16) * 1024 + (r & 7) * 128 + (kc8 & 63) * 2);
    return b ^ ((b >> 3) & 0x70);
}
__device__ __forceinline__ uint32_t tile_off_b(int r, int kc8) {
    uint32_t b = (uint32_t)(((r >> 3) + (kc8 >> 6) * 8) * 1024 + (r & 7) * 128 + (kc8 & 63) * 2);
    return b ^ ((b >> 3) & 0x70);
}
// per-K-step (16 bf16) descriptor offsets, in 16B units
__device__ __forceinline__ uint32_t off_a(int kk) { return (uint32_t)((kk >> 2) * 1024 + (kk & 3) * 2); }
__device__ __forceinline__ uint32_t off_b(int kk) { return (uint32_t)((kk >> 2) * 512  + (kk & 3) * 2); }

#if HAS_TCGEN05
__device__ __forceinline__ void mma_f16_ss(uint32_t d, ull ad, ull bd, uint32_t en) {
    asm volatile(
        "{\n\t"
        ".reg .pred p;\n\t"
        "setp.ne.u32 p, %5, 0;\n\t"
        "tcgen05.mma.cta_group::1.kind::f16 [%0], %1, %2, %3, {%4, %4, %4, %4}, p;\n\t"
        "}"
        :: "r"(d), "l"(ad), "l"(bd), "r"(MMA_IDESC), "r"(0u), "r"(en) : "memory");
}

#define LDTM_X32(r, addr) \
    asm volatile( \
        "tcgen05.ld.sync.aligned.32x32b.x32.b32 " \
        "{%0, %1, %2, %3, %4, %5, %6, %7, " \
        " %8, %9, %10, %11, %12, %13, %14, %15, " \
        " %16, %17, %18, %19, %20, %21, %22, %23, " \
        " %24, %25, %26, %27, %28, %29, %30, %31}, [%32];" \
        : "=r"((r)[0]),  "=r"((r)[1]),  "=r"((r)[2]),  "=r"((r)[3]), \
          "=r"((r)[4]),  "=r"((r)[5]),  "=r"((r)[6]),  "=r"((r)[7]), \
          "=r"((r)[8]),  "=r"((r)[9]),  "=r"((r)[10]), "=r"((r)[11]), \
          "=r"((r)[12]), "=r"((r)[13]), "=r"((r)[14]), "=r"((r)[15]), \
          "=r"((r)[16]), "=r"((r)[17]), "=r"((r)[18]), "=r"((r)[19]), \
          "=r"((r)[20]), "=r"((r)[21]), "=r"((r)[22]), "=r"((r)[23]), \
          "=r"((r)[24]), "=r"((r)[25]), "=r"((r)[26]), "=r"((r)[27]), \
          "=r"((r)[28]), "=r"((r)[29]), "=r"((r)[30]), "=r"((r)[31]) \
        : "r"(addr))
#endif

__device__ __forceinline__ void mbar_wait0(uint32_t mbar) {
    uint32_t done;
    do {
        asm volatile(
            "{\n\t.reg .pred p;\n\t"
            "mbarrier.try_wait.parity.acquire.cta.shared::cta.b64 p, [%1], %2, 0x989680;\n\t"
            "selp.b32 %0, 1, 0, p;\n\t}"
            : "=r"(done) : "r"(mbar), "r"(0u) : "memory");
    } while (!done);
}

// smem layout (dynamic): tmem ptr @0, mbar @8, bias(64f) @512,
// Ahi @1024 (32KB), Alo (32KB), Bhi (16KB), Blo (16KB) -> 99,328 B total
// 2 CTAs/SM fit (194KB < 228KB) -> cross-CTA overlap of loads vs MMA.
#define SO_TM   0
#define SO_MBAR 8
#define SO_BIAS 512
#define SO_AHI  1024
#define SO_ALO  (SO_AHI + 32768)
#define SO_BHI  (SO_ALO + 32768)
#define SO_BLO  (SO_BHI + 16384)
#define SMEM_BYTES (SO_BLO + 16384)

template <int RELU>
__global__ __launch_bounds__(256)
void mma_gemm(const __nv_bfloat16* __restrict__ Ahi, const __nv_bfloat16* __restrict__ Alo,
              const __nv_bfloat16* __restrict__ Bhi, const __nv_bfloat16* __restrict__ Blo,
              const float* __restrict__ bias, float* __restrict__ C,
              int M, int Ncols) {
#if HAS_TCGEN05
    extern __shared__ __align__(16) char smem[];
    const int tid  = threadIdx.x;
    const int wid  = tid >> 5;
    const int lid  = tid & 31;
    const int brow = blockIdx.x * 128;
    const int bcol = blockIdx.y * 64;
    uint32_t sb = smem_u32(smem);

    if (tid == 0)
        asm volatile("mbarrier.init.shared.b64 [%0], 1;" :: "r"(sb + SO_MBAR) : "memory");
    if (wid == 0) {
        asm volatile("tcgen05.alloc.cta_group::1.sync.aligned.shared::cta.b32 [%0], %1;"
                     :: "r"(sb + SO_TM), "r"(64u) : "memory");
        asm volatile("tcgen05.relinquish_alloc_permit.cta_group::1.sync.aligned;");
    }
    if (tid < 64)
        reinterpret_cast<float*>(smem + SO_BIAS)[tid] = bias ? bias[bcol + tid] : 0.0f;

    // phase 1: hi tiles (proven LDG + swizzled-STS staging path).
    // Tail M-block: clamp row index — OOB rows hold duplicate valid data;
    // their D rows are never stored, so this is harmless and race-free.
#pragma unroll
    for (int i = 0; i < 8; i++) {
        int q = tid + 256 * i;
        int r = q >> 4, kc8 = (q & 15) << 3;
        int gr = min(brow + r, M - 1);
        uint4 v = *reinterpret_cast<const uint4*>(Ahi + (long)gr * 128 + kc8);
        *reinterpret_cast<uint4*>(smem + SO_AHI + tile_off_a(r, kc8)) = v;
    }
#pragma unroll
    for (int i = 0; i < 4; i++) {
        int q = tid + 256 * i;
        int r = q >> 4, kc8 = (q & 15) << 3;
        uint4 v = *reinterpret_cast<const uint4*>(Bhi + (long)(bcol + r) * 128 + kc8);
        *reinterpret_cast<uint4*>(smem + SO_BHI + tile_off_b(r, kc8)) = v;
    }
    __syncthreads();

    uint32_t tb;
    asm volatile("ld.shared.b32 %0, [%1];" : "=r"(tb) : "r"(sb + SO_TM));

    ull adh = mk_desc(sb + SO_AHI);
    ull bdh = mk_desc(sb + SO_BHI);
    if (wid == 0 && elect1()) {
        asm volatile("fence.proxy.async.shared::cta;" ::: "memory");
#pragma unroll
        for (int kk = 0; kk < 8; kk++)
            mma_f16_ss(tb, adh + off_a(kk), bdh + off_b(kk), kk > 0 ? 1u : 0u);
    }

    // phase 2: lo tiles — LDGs issued by all threads overlap the in-flight hi MMAs.
#pragma unroll
    for (int i = 0; i < 8; i++) {
        int q = tid + 256 * i;
        int r = q >> 4, kc8 = (q & 15) << 3;
        int gr = min(brow + r, M - 1);
        uint4 v = *reinterpret_cast<const uint4*>(Alo + (long)gr * 128 + kc8);
        *reinterpret_cast<uint4*>(smem + SO_ALO + tile_off_a(r, kc8)) = v;
    }
#pragma unroll
    for (int i = 0; i < 4; i++) {
        int q = tid + 256 * i;
        int r = q >> 4, kc8 = (q & 15) << 3;
        uint4 v = *reinterpret_cast<const uint4*>(Blo + (long)(bcol + r) * 128 + kc8);
        *reinterpret_cast<uint4*>(smem + SO_BLO + tile_off_b(r, kc8)) = v;
    }
    __syncthreads();

    if (wid == 0 && elect1()) {
        asm volatile("fence.proxy.async.shared::cta;" ::: "memory");
        ull adl = mk_desc(sb + SO_ALO);
        ull bdl = mk_desc(sb + SO_BLO);
#pragma unroll
        for (int kk = 0; kk < 8; kk++)
            mma_f16_ss(tb, adh + off_a(kk), bdl + off_b(kk), 1u);
#pragma unroll
        for (int kk = 0; kk < 8; kk++)
            mma_f16_ss(tb, adl + off_a(kk), bdh + off_b(kk), 1u);
        asm volatile("tcgen05.commit.cta_group::1.mbarrier::arrive::one.shared::cluster.b64 [%0];"
                     :: "r"(sb + SO_MBAR) : "memory");
    }

    mbar_wait0(sb + SO_MBAR);
    asm volatile("tcgen05.fence::after_thread_sync;" ::: "memory");

    // epilogue: warps 0-3 -> cols 0-31, warps 4-7 -> cols 32-63; rows by wid&3
    const float* sbias = reinterpret_cast<const float*>(smem + SO_BIAS);
    int cbase = (wid >> 2) * 32;
    int grow  = brow + (wid & 3) * 32 + lid;
    uint32_t dr[32];
    LDTM_X32(dr, tb + cbase);
    asm volatile("tcgen05.wait::ld.sync.aligned;" ::: "memory");
    if (grow < M) {
#pragma unroll
        for (int c = 0; c < 32; c += 4) {
            float4 v;
            v.x = __uint_as_float(dr[c + 0]) + sbias[cbase + c + 0];
            v.y = __uint_as_float(dr[c + 1]) + sbias[cbase + c + 1];
            v.z = __uint_as_float(dr[c + 2]) + sbias[cbase + c + 2];
            v.w = __uint_as_float(dr[c + 3]) + sbias[cbase + c + 3];
            if (RELU) {
                v.x = fmaxf(v.x, 0.f); v.y = fmaxf(v.y, 0.f);
                v.z = fmaxf(v.z, 0.f); v.w = fmaxf(v.w, 0.f);
            }
            *reinterpret_cast<float4*>(C + (long)grow * Ncols + bcol + cbase + c) = v;
        }
    }
    asm volatile("tcgen05.fence::before_thread_sync;" ::: "memory");
    __syncthreads();
    if (wid == 0)
        asm volatile("tcgen05.dealloc.cta_group::1.sync.aligned.b32 %0, %1;"
                     :: "r"(tb), "r"(64u));
#else
    // ---- correct scalar fallback (base-arch compile pass; not expected to run
    //      on the GB300 since the loader prefers the sm_103a cubin) ----
    const int tid  = threadIdx.x;
    const int brow = blockIdx.x * 128;
    const int bcol = blockIdx.y * 64;
    int r  = tid >> 1;
    int gr = brow + r;
    if (gr >= M) return;
    int c0 = (tid & 1) * 32;
    for (int cc = 0; cc < 32; cc++) {
        int col = c0 + cc;
        float acc = bias ? bias[bcol + col] : 0.0f;
        const __nv_bfloat16* ah = Ahi + (long)gr * 128;
        const __nv_bfloat16* al = Alo + (long)gr * 128;
        const __nv_bfloat16* bh = Bhi + (long)(bcol + col) * 128;
        const __nv_bfloat16* bl = Blo + (long)(bcol + col) * 128;
        for (int k = 0; k < 128; k++) {
            float a = __bfloat162float(ah[k]) + __bfloat162float(al[k]);
            float b = __bfloat162float(bh[k]) + __bfloat162float(bl[k]);
            acc += a * b;
        }
        if (RELU) acc = fmaxf(acc, 0.0f);
        C[(long)gr * Ncols + bcol + col] = acc;
    }
#endif
}

// ---------------- weight conversion (once per launch) ------------------------
__global__ void cvt_pair(const float* __restrict__ src, __nv_bfloat16* __restrict__ hi,
                         __nv_bfloat16* __restrict__ lo, int n4) {
    int idx = blockIdx.x * blockDim.x + threadIdx.x;
    if (idx >= n4) return;
    float4 v = reinterpret_cast<const float4*>(src)[idx];
    ushort4 h, l;
    __nv_bfloat16 bh, bl;
    split_bf16(v.x, bh, bl); h.x = __bfloat16_as_ushort(bh); l.x = __bfloat16_as_ushort(bl);
    split_bf16(v.y, bh, bl); h.y = __bfloat16_as_ushort(bh); l.y = __bfloat16_as_ushort(bl);
    split_bf16(v.z, bh, bl); h.z = __bfloat16_as_ushort(bh); l.z = __bfloat16_as_ushort(bl);
    split_bf16(v.w, bh, bl); h.w = __bfloat16_as_ushort(bh); l.w = __bfloat16_as_ushort(bl);
    reinterpret_cast<ushort4*>(hi)[idx] = h;
    reinterpret_cast<ushort4*>(lo)[idx] = l;
}

// transpose each 128x128 matrix: out[m][co][k] = in[m][k][co]
__global__ void cvt_trans(const float* __restrict__ src, __nv_bfloat16* __restrict__ hi,
                          __nv_bfloat16* __restrict__ lo, int nmat) {
    int idx = blockIdx.x * blockDim.x + threadIdx.x;
    if (idx >= nmat * 16384) return;
    int m  = idx >> 14;
    int co = (idx >> 7) & 127;
    int k  = idx & 127;
    float v = src[m * 16384 + k * 128 + co];
    __nv_bfloat16 bh, bl;
    split_bf16(v, bh, bl);
    hi[idx] = bh;
    lo[idx] = bl;
}

// copy/convert activation: dstf (optional) = src; hi/lo = bf16 split of src
__global__ void copy_cvt(const float* __restrict__ src, float* __restrict__ dstf,
                         __nv_bfloat16* __restrict__ hi, __nv_bfloat16* __restrict__ lo) {
    int idx = blockIdx.x * blockDim.x + threadIdx.x;
    if (idx >= NNODES * 32) return;
    float4 v = reinterpret_cast<const float4*>(src)[idx];
    if (dstf) reinterpret_cast<float4*>(dstf)[idx] = v;
    ushort4 h, l;
    __nv_bfloat16 bh, bl;
    split_bf16(v.x, bh, bl); h.x = __bfloat16_as_ushort(bh); l.x = __bfloat16_as_ushort(bl);
    split_bf16(v.y, bh, bl); h.y = __bfloat16_as_ushort(bh); l.y = __bfloat16_as_ushort(bl);
    split_bf16(v.z, bh, bl); h.z = __bfloat16_as_ushort(bh); l.z = __bfloat16_as_ushort(bl);
    split_bf16(v.w, bh, bl); h.w = __bfloat16_as_ushort(bh); l.w = __bfloat16_as_ushort(bl);
    reinterpret_cast<ushort4*>(hi)[idx] = h;
    reinterpret_cast<ushort4*>(lo)[idx] = l;
}

// ---------------- feature build ---------------------------------------------
__global__ void build_features(const int* __restrict__ xt,
                               const int* __restrict__ xtok,
                               const float* __restrict__ xs) {
    int idx = blockIdx.x * blockDim.x + threadIdx.x;
    if (idx >= NNODES * CDIM) return;
    int n = idx >> 7;
    int c = idx & 127;
    float v;
    if (c < 32) {
        v = (c == xt[n]) ? 1.0f : 0.0f;
    } else if (c < 126) {
        int tok = xtok[n];
        tok = min(max(tok, 0), 93);
        v = ((c - 32) == tok) ? 1.0f : 0.0f;
    } else {
        v = xs[n * 2 + (c - 126)];
    }
    g_h[idx] = v;
}

// ---------------- edge bucketing (block-aggregated atomics) ------------------
__global__ void count_et_blk(const int* __restrict__ et) {
    __shared__ int loc[3];
    if (threadIdx.x < 3) loc[threadIdx.x] = 0;
    __syncthreads();
    int e = blockIdx.x * blockDim.x + threadIdx.x;
    if (e < NEDGES) atomicAdd(&loc[et[e]], 1);
    __syncthreads();
    if (threadIdx.x < 3 && loc[threadIdx.x] > 0) atomicAdd(&g_cnt[threadIdx.x], loc[threadIdx.x]);
}
__global__ void prefix_et() {
    g_off[0] = 0;
    g_off[1] = g_cnt[0];
    g_off[2] = g_cnt[0] + g_cnt[1];
    g_off[3] = g_cnt[0] + g_cnt[1] + g_cnt[2];
    g_cur[0] = 0;
    g_cur[1] = g_cnt[0];
    g_cur[2] = g_cnt[0] + g_cnt[1];
}
__global__ void bucket_et_blk(const int* __restrict__ ei, const int* __restrict__ et) {
    __shared__ int loc[3], base[3];
    if (threadIdx.x < 3) loc[threadIdx.x] = 0;
    __syncthreads();
    int e = blockIdx.x * blockDim.x + threadIdx.x;
    int t = 0, rank = 0;
    bool valid = (e < NEDGES);
    if (valid) {
        t = et[e];
        rank = atomicAdd(&loc[t], 1);
    }
    __syncthreads();
    if (threadIdx.x < 3) base[threadIdx.x] = (loc[threadIdx.x] > 0) ? atomicAdd(&g_cur[threadIdx.x], loc[threadIdx.x]) : 0;
    __syncthreads();
    if (valid) {
        int p = base[t] + rank;
        g_es[p] = ei[e];
        g_ed[p] = ei[NEDGES + e];
    }
}

// ---------------- scatter-add over bucketed edges (v4 reductions) ------------
__global__ void scatter_add(int t) {
    long idx = (long)blockIdx.x * blockDim.x + threadIdx.x;
    int e = (int)(idx >> 5);
    int lo = g_off[t], hi = g_off[t + 1];
    if (e < lo || e >= hi) return;
    int lane = (int)(idx & 31);
    int s = g_es[e];
    int d = g_ed[e];
    float4 v = *reinterpret_cast<const float4*>(g_x + (long)s * 128 + lane * 4);
    float* o = g_agg + (long)d * 128 + lane * 4;
    asm volatile("red.global.add.v4.f32 [%0], {%1, %2, %3, %4};"
                 :: "l"(o), "f"(v.x), "f"(v.y), "f"(v.z), "f"(v.w) : "memory");
}

// ---------------- GRU gate + bf16 split of new m + optional total accum ------
__global__ void gru_gate(int addTot) {
    int idx = blockIdx.x * blockDim.x + threadIdx.x;
    if (idx >= NNODES * 32) return;
    int n  = idx >> 5;
    int c4 = (idx & 31) * 4;
    const float* gi = g_gi + (long)n * K3C;
    const float* gh = g_gh + (long)n * K3C;
    float4 gir = *reinterpret_cast<const float4*>(gi + c4);
    float4 ghr = *reinterpret_cast<const float4*>(gh + c4);
    float4 giz = *reinterpret_cast<const float4*>(gi + 128 + c4);
    float4 ghz = *reinterpret_cast<const float4*>(gh + 128 + c4);
    float4 gin = *reinterpret_cast<const float4*>(gi + 256 + c4);
    float4 ghn = *reinterpret_cast<const float4*>(gh + 256 + c4);
    float4 hv  = *reinterpret_cast<const float4*>(g_m + (long)n * 128 + c4);
    float4 res;
#pragma unroll
    for (int j = 0; j < 4; j++) {
        float r  = 1.0f / (1.0f + expf(-((&gir.x)[j] + (&ghr.x)[j])));
        float z  = 1.0f / (1.0f + expf(-((&giz.x)[j] + (&ghz.x)[j])));
        float ng = tanhf((&gin.x)[j] + r * (&ghn.x)[j]);
        (&res.x)[j] = (1.0f - z) * ng + z * (&hv.x)[j];
    }
    *reinterpret_cast<float4*>(g_m + (long)n * 128 + c4) = res;
    ushort4 h, l;
    __nv_bfloat16 bh, bl;
    split_bf16(res.x, bh, bl); h.x = __bfloat16_as_ushort(bh); l.x = __bfloat16_as_ushort(bl);
    split_bf16(res.y, bh, bl); h.y = __bfloat16_as_ushort(bh); l.y = __bfloat16_as_ushort(bl);
    split_bf16(res.z, bh, bl); h.z = __bfloat16_as_ushort(bh); l.z = __bfloat16_as_ushort(bl);
    split_bf16(res.w, bh, bl); h.w = __bfloat16_as_ushort(bh); l.w = __bfloat16_as_ushort(bl);
    reinterpret_cast<ushort4*>(g_mhi)[idx] = h;
    reinterpret_cast<ushort4*>(g_mlo)[idx] = l;
    if (addTot) {
        float4 tv = *reinterpret_cast<const float4*>(g_tot + (long)n * 128 + c4);
        tv.x += res.x; tv.y += res.y; tv.z += res.z; tv.w += res.w;
        *reinterpret_cast<float4*>(g_tot + (long)n * 128 + c4) = tv;
    }
}

// ---------------- LayerNorm(residual) + ReLU ---------------------------------
__global__ void ln_relu(const float* __restrict__ gam, const float* __restrict__ bet) {
    int n = blockIdx.x;
    int c = threadIdx.x;
    float v  = g_h[(long)n * 128 + c] + g_tot[(long)n * 128 + c];
    float s  = v;
    float s2 = v * v;
#pragma unroll
    for (int o = 16; o; o >>= 1) {
        s  += __shfl_xor_sync(0xffffffffu, s,  o);
        s2 += __shfl_xor_sync(0xffffffffu, s2, o);
    }
    __shared__ float sh[4], sh2[4];
    int w = c >> 5;
    if ((c & 31) == 0) { sh[w] = s; sh2[w] = s2; }
    __syncthreads();
    s  = sh[0] + sh[1] + sh[2] + sh[3];
    s2 = sh2[0] + sh2[1] + sh2[2] + sh2[3];
    float mu  = s * (1.0f / 128.0f);
    float var = s2 * (1.0f / 128.0f) - mu * mu;
    float o = (v - mu) * rsqrtf(var + 1e-5f) * gam[c] + bet[c];
    g_h[(long)n * 128 + c] = fmaxf(o, 0.0f);
}

// ---------------- final tiny head: out = z @ w2^T + b2 -----------------------
__global__ void head2(const float* __restrict__ w2, const float* __restrict__ b2,
                      float* __restrict__ out) {
    int gw = (blockIdx.x * blockDim.x + threadIdx.x) >> 5;
    if (gw >= NNODES) return;
    int lane = threadIdx.x & 31;
    float4 zv = *reinterpret_cast<const float4*>(g_z + (long)gw * 128 + lane * 4);
    float4 w0 = *reinterpret_cast<const float4*>(w2 + lane * 4);
    float4 w1 = *reinterpret_cast<const float4*>(w2 + 128 + lane * 4);
    float p0 = zv.x * w0.x + zv.y * w0.y + zv.z * w0.z + zv.w * w0.w;
    float p1 = zv.x * w1.x + zv.y * w1.y + zv.z * w1.z + zv.w * w1.w;
#pragma unroll
    for (int o = 16; o; o >>= 1) {
        p0 += __shfl_xor_sync(0xffffffffu, p0, o);
        p1 += __shfl_xor_sync(0xffffffffu, p1, o);
    }
    if (lane == 0) {
        out[gw * 2 + 0] = p0 + b2[0];
        out[gw * 2 + 1] = p1 + b2[1];
    }
}

// ---------------- host orchestration -----------------------------------------
extern "C" void kernel_launch(void* const* d_in, const int* in_sizes, int n_in,
                              void* d_out, int out_size) {
    const int*   x_type  = (const int*)d_in[0];
    const int*   x_tok   = (const int*)d_in[1];
    const float* x_small = (const float*)d_in[2];
    const int*   ei      = (const int*)d_in[3];
    const int*   et      = (const int*)d_in[4];
    const float* conv_w  = (const float*)d_in[5];
    const float* wih     = (const float*)d_in[6];
    const float* whh     = (const float*)d_in[7];
    const float* bih     = (const float*)d_in[8];
    const float* bhh     = (const float*)d_in[9];
    const float* ln_g    = (const float*)d_in[10];
    const float* ln_b    = (const float*)d_in[11];
    const float* hw1     = (const float*)d_in[12];
    const float* hb1     = (const float*)d_in[13];
    const float* hw2     = (const float*)d_in[14];
    const float* hb2     = (const float*)d_in[15];
    float* out = (float*)d_out;

    cudaFuncSetAttribute(mma_gemm<0>, cudaFuncAttributeMaxDynamicSharedMemorySize, SMEM_BYTES);
    cudaFuncSetAttribute(mma_gemm<1>, cudaFuncAttributeMaxDynamicSharedMemorySize, SMEM_BYTES);

    float *h_, *m_, *x_, *agg_, *tot_, *gi_, *gh_, *z_;
    __nv_bfloat16 *mhi_, *mlo_, *ahi_, *alo_;
    __nv_bfloat16 *wihh_, *wihl_, *whhh_, *whhl_, *cwh_, *cwl_, *w1h_, *w1l_;
    int* cnt_;
    cudaGetSymbolAddress((void**)&h_,   g_h);
    cudaGetSymbolAddress((void**)&m_,   g_m);
    cudaGetSymbolAddress((void**)&x_,   g_x);
    cudaGetSymbolAddress((void**)&agg_, g_agg);
    cudaGetSymbolAddress((void**)&tot_, g_tot);
    cudaGetSymbolAddress((void**)&gi_,  g_gi);
    cudaGetSymbolAddress((void**)&gh_,  g_gh);
    cudaGetSymbolAddress((void**)&z_,   g_z);
    cudaGetSymbolAddress((void**)&mhi_, g_mhi);
    cudaGetSymbolAddress((void**)&mlo_, g_mlo);
    cudaGetSymbolAddress((void**)&ahi_, g_ahi);
    cudaGetSymbolAddress((void**)&alo_, g_alo);
    cudaGetSymbolAddress((void**)&wihh_, g_wihh);
    cudaGetSymbolAddress((void**)&wihl_, g_wihl);
    cudaGetSymbolAddress((void**)&whhh_, g_whhh);
    cudaGetSymbolAddress((void**)&whhl_, g_whhl);
    cudaGetSymbolAddress((void**)&cwh_, g_cwh);
    cudaGetSymbolAddress((void**)&cwl_, g_cwl);
    cudaGetSymbolAddress((void**)&w1h_, g_w1h);
    cudaGetSymbolAddress((void**)&w1l_, g_w1l);
    cudaGetSymbolAddress((void**)&cnt_, g_cnt);

    const size_t NC_BYTES = (size_t)NNODES * CDIM * sizeof(float);
    const int NC_GRID = (NNODES * CDIM + 255) / 256;
    const int NQ_GRID = (NNODES * 32 + 255) / 256;
    const int E_GRID  = (NEDGES + 255) / 256;
    const int SC_GRID = (int)(((long)NEDGES * 32 + 255) / 256);

    build_features<<<NC_GRID, 256>>>(x_type, x_tok, x_small);

    cudaMemsetAsync(cnt_, 0, 3 * sizeof(int));
    count_et_blk<<<E_GRID, 256>>>(et);
    prefix_et<<<1, 1>>>();
    bucket_et_blk<<<E_GRID, 256>>>(ei, et);

    // weight conversion (once per launch)
    cvt_pair<<<(6 * K3C * CDIM / 4 + 255) / 256, 256>>>(wih, wihh_, wihl_, 6 * K3C * CDIM / 4);
    cvt_pair<<<(6 * K3C * CDIM / 4 + 255) / 256, 256>>>(whh, whhh_, whhl_, 6 * K3C * CDIM / 4);
    cvt_pair<<<(CDIM * CDIM / 4 + 255) / 256, 256>>>(hw1, w1h_, w1l_, CDIM * CDIM / 4);
    cvt_trans<<<(18 * CDIM * CDIM + 255) / 256, 256>>>(conv_w, cwh_, cwl_, 18);

    const int MT = (NNODES + 127) / 128;
    dim3 g1(MT, CDIM / 64);   // 128-col outputs
    dim3 g3(MT, K3C / 64);    // 384-col outputs

    for (int b = 0; b < 2; b++) {
        cudaMemsetAsync(tot_, 0, NC_BYTES);
        for (int t = 0; t < 3; t++) {
            copy_cvt<<<NQ_GRID, 256>>>(h_, m_, mhi_, mlo_);
            for (int s = 0; s < 3; s++) {
                int mi = ((b * 3) + t) * 3 + s;
                mma_gemm<0><<<g1, 256, SMEM_BYTES>>>(mhi_, mlo_,
                    cwh_ + (size_t)mi * CDIM * CDIM, cwl_ + (size_t)mi * CDIM * CDIM,
                    nullptr, x_, NNODES, CDIM);
                cudaMemsetAsync(agg_, 0, NC_BYTES);
                scatter_add<<<SC_GRID, 256>>>(t);
                copy_cvt<<<NQ_GRID, 256>>>(agg_, nullptr, ahi_, alo_);
                int wi = b * 3 + t;
                mma_gemm<0><<<g3, 256, SMEM_BYTES>>>(ahi_, alo_,
                    wihh_ + (size_t)wi * K3C * CDIM, wihl_ + (size_t)wi * K3C * CDIM,
                    bih + (size_t)wi * K3C, gi_, NNODES, K3C);
                mma_gemm<0><<<g3, 256, SMEM_BYTES>>>(mhi_, mlo_,
                    whhh_ + (size_t)wi * K3C * CDIM, whhl_ + (size_t)wi * K3C * CDIM,
                    bhh + (size_t)wi * K3C, gh_, NNODES, K3C);
                gru_gate<<<NQ_GRID, 256>>>(s == 2 ? 1 : 0);
            }
        }
        ln_relu<<<NNODES, 128>>>(ln_g + b * 128, ln_b + b * 128);
    }

    copy_cvt<<<NQ_GRID, 256>>>(h_, nullptr, mhi_, mlo_);
    mma_gemm<1><<<g1, 256, SMEM_BYTES>>>(mhi_, mlo_, w1h_, w1l_, hb1, z_, NNODES, CDIM);
    head2<<<(NNODES * 32 + 255) / 256, 256>>>(hw2, hb2, out);
}